// round 1
// baseline (speedup 1.0000x reference)
#include <cuda_runtime.h>
#include <cuda_bf16.h>

// Problem constants (fixed shapes per reference setup_inputs)
#define T_STEPS 2048
#define BATCH   16
#define DIM     1024
#define M_TOT   (T_STEPS * BATCH)   // 32768

// Scratch for the two GEMM outputs (sanctioned __device__ global scratch)
__device__ float g_wx[(size_t)M_TOT * DIM];
__device__ float g_gate[(size_t)M_TOT * DIM];

__device__ __forceinline__ float sigmoidf_(float v) {
    return 1.0f / (1.0f + __expf(-v));
}

// ---------------------------------------------------------------------------
// SGEMM (NT): C[m,n] = sum_k A[m,k] * B[n,k] + bias[n], optional sigmoid.
// A: [M,K] row-major, B: [N,K] row-major. BM=BN=128, BK=16, 256 threads,
// 8x8 accumulators per thread, register-prefetched global loads.
// ---------------------------------------------------------------------------
#define BM 128
#define BN 128
#define BK 16
#define TM 8
#define TN 8

template<bool GATE>
__global__ __launch_bounds__(256)
void gemm_nt_kernel(const float* __restrict__ A,
                    const float* __restrict__ B,
                    const float* __restrict__ bias,
                    float* __restrict__ C,
                    int M, int N, int K)
{
    __shared__ float As[BK][BM];
    __shared__ float Bs[BK][BN];

    const int tid = threadIdx.x;               // 0..255
    const int bm  = blockIdx.x;                // M/128 tiles
    const int bn  = blockIdx.y;                // N/128 tiles

    // Global-load mapping: each thread loads 8 consecutive floats (2 float4)
    // from one row of the 128x16 tile.
    const int lrow  = tid >> 1;                // 0..127
    const int lcol  = (tid & 1) * 8;           // 0 or 8
    const float* Aptr = A + (size_t)(bm * BM + lrow) * K + lcol;
    const float* Bptr = B + (size_t)(bn * BN + lrow) * K + lcol;

    // Compute mapping: 16x16 thread grid, 8x8 outputs each
    const int tx = (tid & 15) * TN;            // col offset in tile
    const int ty = (tid >> 4) * TM;            // row offset in tile

    float acc[TM][TN];
    #pragma unroll
    for (int i = 0; i < TM; i++)
        #pragma unroll
        for (int j = 0; j < TN; j++) acc[i][j] = 0.0f;

    // Prefetch first tile into registers
    float4 a0 = *(const float4*)(Aptr + 0);
    float4 a1 = *(const float4*)(Aptr + 4);
    float4 b0 = *(const float4*)(Bptr + 0);
    float4 b1 = *(const float4*)(Bptr + 4);

    for (int k0 = 0; k0 < K; k0 += BK) {
        // Stage current prefetch into shared (transposed: [k][m])
        As[lcol + 0][lrow] = a0.x; As[lcol + 1][lrow] = a0.y;
        As[lcol + 2][lrow] = a0.z; As[lcol + 3][lrow] = a0.w;
        As[lcol + 4][lrow] = a1.x; As[lcol + 5][lrow] = a1.y;
        As[lcol + 6][lrow] = a1.z; As[lcol + 7][lrow] = a1.w;
        Bs[lcol + 0][lrow] = b0.x; Bs[lcol + 1][lrow] = b0.y;
        Bs[lcol + 2][lrow] = b0.z; Bs[lcol + 3][lrow] = b0.w;
        Bs[lcol + 4][lrow] = b1.x; Bs[lcol + 5][lrow] = b1.y;
        Bs[lcol + 6][lrow] = b1.z; Bs[lcol + 7][lrow] = b1.w;
        __syncthreads();

        // Prefetch next tile while computing this one
        if (k0 + BK < K) {
            a0 = *(const float4*)(Aptr + k0 + BK + 0);
            a1 = *(const float4*)(Aptr + k0 + BK + 4);
            b0 = *(const float4*)(Bptr + k0 + BK + 0);
            b1 = *(const float4*)(Bptr + k0 + BK + 4);
        }

        #pragma unroll
        for (int k = 0; k < BK; k++) {
            float af[TM], bf[TN];
            *(float4*)(af + 0) = *(const float4*)&As[k][ty + 0];
            *(float4*)(af + 4) = *(const float4*)&As[k][ty + 4];
            *(float4*)(bf + 0) = *(const float4*)&Bs[k][tx + 0];
            *(float4*)(bf + 4) = *(const float4*)&Bs[k][tx + 4];
            #pragma unroll
            for (int i = 0; i < TM; i++)
                #pragma unroll
                for (int j = 0; j < TN; j++)
                    acc[i][j] = fmaf(af[i], bf[j], acc[i][j]);
        }
        __syncthreads();
    }

    // Epilogue: + bias, optional sigmoid, vectorized store
    const int crow0 = bm * BM + ty;
    const int ccol0 = bn * BN + tx;
    float bv[TN];
    #pragma unroll
    for (int j = 0; j < TN; j++) bv[j] = __ldg(bias + ccol0 + j);

    #pragma unroll
    for (int i = 0; i < TM; i++) {
        float4 o0, o1;
        float v[TN];
        #pragma unroll
        for (int j = 0; j < TN; j++) {
            float t = acc[i][j] + bv[j];
            v[j] = GATE ? sigmoidf_(t) : t;
        }
        o0.x = v[0]; o0.y = v[1]; o0.z = v[2]; o0.w = v[3];
        o1.x = v[4]; o1.y = v[5]; o1.z = v[6]; o1.w = v[7];
        float* cp = C + (size_t)(crow0 + i) * N + ccol0;
        *(float4*)(cp + 0) = o0;
        *(float4*)(cp + 4) = o1;
    }
}

// ---------------------------------------------------------------------------
// Sequential scan: one CTA per batch row (16 CTAs), 256 threads, 4 elems/thr.
// h kept in registers; one block reduce (sum of squares) per step.
// out layout: d_out = [outs (T*B*D) | h ((T+1)*B*D, row 0 = h0)]
// ---------------------------------------------------------------------------
__global__ __launch_bounds__(256)
void scan_kernel(const float* __restrict__ h0,
                 const float* __restrict__ wx,
                 const float* __restrict__ gate,
                 float* __restrict__ out_o,
                 float* __restrict__ out_h)
{
    const int b    = blockIdx.x;       // batch row
    const int tid  = threadIdx.x;      // 0..255
    const int lane = tid & 31;
    const int wid  = tid >> 5;         // 0..7
    const int d    = tid * 4;

    __shared__ float red[2][8];

    // init h from h0, and emit h row 0 (= h0)
    float4 h = *(const float4*)(h0 + b * DIM + d);
    *(float4*)(out_h + b * DIM + d) = h;

    const int base   = b * DIM + d;    // index for t=0
    const int tstride = BATCH * DIM;   // 16384

    float4 g = *(const float4*)(gate + base);
    float4 w = *(const float4*)(wx + base);

    for (int t = 0; t < T_STEPS; t++) {
        // prefetch next step's inputs
        float4 gn, wn;
        if (t + 1 < T_STEPS) {
            const int nb = base + (t + 1) * tstride;
            gn = *(const float4*)(gate + nb);
            wn = *(const float4*)(wx + nb);
        }

        // gated residual
        float4 hn;
        hn.x = fmaf(g.x, w.x, h.x);
        hn.y = fmaf(g.y, w.y, h.y);
        hn.z = fmaf(g.z, w.z, h.z);
        hn.w = fmaf(g.w, w.w, h.w);

        // block reduce sum of squares
        float s = hn.x * hn.x + hn.y * hn.y + hn.z * hn.z + hn.w * hn.w;
        #pragma unroll
        for (int o = 16; o > 0; o >>= 1)
            s += __shfl_xor_sync(0xffffffffu, s, o);
        if (lane == 0) red[t & 1][wid] = s;
        __syncthreads();
        float tot = 0.0f;
        #pragma unroll
        for (int i = 0; i < 8; i++) tot += red[t & 1][i];

        // RMSNorm
        const float rstd = rsqrtf(tot * (1.0f / (float)DIM) + 1e-6f);
        h.x = hn.x * rstd; h.y = hn.y * rstd;
        h.z = hn.z * rstd; h.w = hn.w * rstd;

        // out = h * silu(h) = h^2 * sigmoid(h)
        float4 o4;
        o4.x = h.x * h.x * sigmoidf_(h.x);
        o4.y = h.y * h.y * sigmoidf_(h.y);
        o4.z = h.z * h.z * sigmoidf_(h.z);
        o4.w = h.w * h.w * sigmoidf_(h.w);

        const int ob = t * tstride + base;
        *(float4*)(out_o + ob) = o4;
        *(float4*)(out_h + ob + tstride) = h;   // h row (t+1)

        g = gn; w = wn;
    }
}

// ---------------------------------------------------------------------------
// Launch
// ---------------------------------------------------------------------------
extern "C" void kernel_launch(void* const* d_in, const int* in_sizes, int n_in,
                              void* d_out, int out_size)
{
    const float* x   = (const float*)d_in[0];  // [T, B, D] -> [M, K]
    const float* h0  = (const float*)d_in[1];  // [B, D]
    const float* W   = (const float*)d_in[2];  // [D, D] (e, d)
    const float* Wg  = (const float*)d_in[3];  // [D, D]
    const float* b   = (const float*)d_in[4];  // [D]
    const float* bg  = (const float*)d_in[5];  // [D]

    float* out   = (float*)d_out;
    float* out_o = out;                                   // [T, B, D]
    float* out_h = out + (size_t)T_STEPS * BATCH * DIM;   // [T+1, B, D]

    float* wx_ptr = nullptr;
    float* gt_ptr = nullptr;
    cudaGetSymbolAddress((void**)&wx_ptr, g_wx);
    cudaGetSymbolAddress((void**)&gt_ptr, g_gate);

    dim3 grid(M_TOT / BM, DIM / BN);   // (256, 8)
    gemm_nt_kernel<false><<<grid, 256>>>(x, W,  b,  wx_ptr, M_TOT, DIM, DIM);
    gemm_nt_kernel<true ><<<grid, 256>>>(x, Wg, bg, gt_ptr, M_TOT, DIM, DIM);
    scan_kernel<<<BATCH, 256>>>(h0, wx_ptr, gt_ptr, out_o, out_h);
}

// round 3
// speedup vs baseline: 1.6878x; 1.6878x over previous
#include <cuda_runtime.h>
#include <cuda_bf16.h>
#include <cstdint>

#define T_STEPS 2048
#define BATCH   16
#define DIM     1024
#define M_TOT   (T_STEPS * BATCH)   // 32768

// ---------------- GEMM tiling ----------------
#define BM 128
#define BN 128
#define BK 32
#define NCHUNK (DIM / BK)       // 32
#define NSTAGES 4

#define RSTR 80                 // padded smem row stride in bytes (40 bf16)
#define MATB (128 * RSTR)       // 10240 bytes per 128x32 bf16 matrix tile
#define OFF_AH 0
#define OFF_AL (1 * MATB)
#define OFF_BH (2 * MATB)
#define OFF_BL (3 * MATB)
#define STG    (4 * MATB)       // 40960 per stage
#define SMEM_TOTAL (NSTAGES * STG)  // 163840

// ---------------- scratch ----------------
__device__ __nv_bfloat16 g_xhi[(size_t)M_TOT * DIM];
__device__ __nv_bfloat16 g_xlo[(size_t)M_TOT * DIM];
__device__ __nv_bfloat16 g_whi[DIM * DIM], g_wlo[DIM * DIM];
__device__ __nv_bfloat16 g_vhi[DIM * DIM], g_vlo[DIM * DIM];
__device__ float g_wx[(size_t)M_TOT * DIM];
__device__ float g_gate[(size_t)M_TOT * DIM];

// ---------------- helpers ----------------
__device__ __forceinline__ uint32_t smem_u32(const void* p) {
    uint32_t a;
    asm("{ .reg .u64 t; cvta.to.shared.u64 t, %1; cvt.u32.u64 %0, t; }" : "=r"(a) : "l"(p));
    return a;
}
__device__ __forceinline__ void cpasync16(uint32_t dst, const void* src) {
    asm volatile("cp.async.cg.shared.global [%0], [%1], 16;" :: "r"(dst), "l"(src));
}
__device__ __forceinline__ void cp_commit() { asm volatile("cp.async.commit_group;"); }
__device__ __forceinline__ void cp_wait2()  { asm volatile("cp.async.wait_group 2;"); }

__device__ __forceinline__ void ldm_x4(uint32_t& r0, uint32_t& r1, uint32_t& r2, uint32_t& r3,
                                       uint32_t addr) {
    asm volatile("ldmatrix.sync.aligned.m8n8.x4.shared.b16 {%0,%1,%2,%3}, [%4];"
                 : "=r"(r0), "=r"(r1), "=r"(r2), "=r"(r3) : "r"(addr));
}
__device__ __forceinline__ void mma16816(float* c, const uint32_t* a, const uint32_t* b) {
    asm volatile(
        "mma.sync.aligned.m16n8k16.row.col.f32.bf16.bf16.f32 "
        "{%0,%1,%2,%3}, {%4,%5,%6,%7}, {%8,%9}, {%0,%1,%2,%3};"
        : "+f"(c[0]), "+f"(c[1]), "+f"(c[2]), "+f"(c[3])
        : "r"(a[0]), "r"(a[1]), "r"(a[2]), "r"(a[3]), "r"(b[0]), "r"(b[1]));
}
__device__ __forceinline__ float sigmoidf_(float v) {
    return 1.0f / (1.0f + __expf(-v));
}

// ---------------- fp32 -> bf16 hi/lo split ----------------
__global__ __launch_bounds__(256)
void split_kernel(const float* __restrict__ s,
                  __nv_bfloat16* __restrict__ hi,
                  __nv_bfloat16* __restrict__ lo, int n4)
{
    int i = blockIdx.x * blockDim.x + threadIdx.x;
    if (i >= n4) return;
    float4 v = ((const float4*)s)[i];
    float a[4] = {v.x, v.y, v.z, v.w};
    __nv_bfloat16 h[4], l[4];
    #pragma unroll
    for (int j = 0; j < 4; j++) {
        h[j] = __float2bfloat16(a[j]);
        l[j] = __float2bfloat16(a[j] - __bfloat162float(h[j]));
    }
    ((__nv_bfloat162*)hi)[i * 2 + 0] = __nv_bfloat162(h[0], h[1]);
    ((__nv_bfloat162*)hi)[i * 2 + 1] = __nv_bfloat162(h[2], h[3]);
    ((__nv_bfloat162*)lo)[i * 2 + 0] = __nv_bfloat162(l[0], l[1]);
    ((__nv_bfloat162*)lo)[i * 2 + 1] = __nv_bfloat162(l[2], l[3]);
}

// ---------------- HMMA GEMM (bf16 x3 split, NT) ----------------
__device__ __forceinline__ void load_chunk(uint32_t sbase,
                                           const __nv_bfloat16* Ah, const __nv_bfloat16* Al,
                                           const __nv_bfloat16* Bh, const __nv_bfloat16* Bl,
                                           int k0)
{
    const int tid = threadIdx.x;
    #pragma unroll
    for (int j = 0; j < 2; j++) {
        int c   = tid + j * 256;       // 0..511
        int row = c >> 2;              // 0..127
        int cc  = c & 3;               // 16B chunk within row
        uint32_t so = (uint32_t)(row * RSTR + cc * 16);
        size_t   go = (size_t)row * DIM + k0 + cc * 8;
        cpasync16(sbase + OFF_AH + so, Ah + go);
        cpasync16(sbase + OFF_AL + so, Al + go);
        cpasync16(sbase + OFF_BH + so, Bh + go);
        cpasync16(sbase + OFF_BL + so, Bl + go);
    }
}

__global__ __launch_bounds__(256, 1)
void gemm_kernel(const __nv_bfloat16* __restrict__ xhi, const __nv_bfloat16* __restrict__ xlo,
                 const __nv_bfloat16* __restrict__ whi, const __nv_bfloat16* __restrict__ wlo,
                 const __nv_bfloat16* __restrict__ vhi, const __nv_bfloat16* __restrict__ vlo,
                 const float* __restrict__ bias0, const float* __restrict__ bias1,
                 float* __restrict__ wx, float* __restrict__ gate)
{
    extern __shared__ char smem[];
    const uint32_t sb = smem_u32(smem);
    const int tid  = threadIdx.x;
    const int wid  = tid >> 5;
    const int lane = tid & 31;
    const int bn = blockIdx.x, bm = blockIdx.y, z = blockIdx.z;

    const __nv_bfloat16* Ah = xhi + (size_t)bm * BM * DIM;
    const __nv_bfloat16* Al = xlo + (size_t)bm * BM * DIM;
    const __nv_bfloat16* Bh = (z ? vhi : whi) + (size_t)bn * BN * DIM;
    const __nv_bfloat16* Bl = (z ? vlo : wlo) + (size_t)bn * BN * DIM;
    const float* bias = z ? bias1 : bias0;
    float* C = z ? gate : wx;

    // warp tile: 2 x 4 warps, 64 x 32 each
    const int wm0 = (wid & 1) * 64;    // warp row origin in tile
    const int wn0 = (wid >> 1) * 32;   // warp col origin in tile

    // ldmatrix per-lane byte offsets (within a matrix region)
    const uint32_t a_lane = (uint32_t)((lane & 15) * RSTR + (lane >> 4) * 16);
    const int g = lane >> 3;
    const uint32_t b_lane = (uint32_t)(((g >> 1) * 8 + (lane & 7)) * RSTR + (g & 1) * 16);

    float acc[4][4][4];
    #pragma unroll
    for (int mi = 0; mi < 4; mi++)
        #pragma unroll
        for (int ni = 0; ni < 4; ni++)
            #pragma unroll
            for (int r = 0; r < 4; r++) acc[mi][ni][r] = 0.0f;

    // prologue: 3 chunks in flight
    #pragma unroll
    for (int p = 0; p < 3; p++) {
        load_chunk(sb + p * STG, Ah, Al, Bh, Bl, p * BK);
        cp_commit();
    }

    for (int i = 0; i < NCHUNK; i++) {
        cp_wait2();
        __syncthreads();

        if (i + 3 < NCHUNK)
            load_chunk(sb + ((i + 3) & 3) * STG, Ah, Al, Bh, Bl, (i + 3) * BK);
        cp_commit();

        const uint32_t stg = sb + (uint32_t)(i & 3) * STG;
        const uint32_t aBase = stg + (uint32_t)(wm0 * RSTR) + a_lane;
        const uint32_t bBase = stg + (uint32_t)(wn0 * RSTR) + b_lane;

        #pragma unroll
        for (int ks = 0; ks < 2; ks++) {
            const uint32_t ko = (uint32_t)(ks * 32);
            uint32_t aH[4][4], aL[4][4], bH[4][2], bL[4][2];
            #pragma unroll
            for (int mi = 0; mi < 4; mi++)
                ldm_x4(aH[mi][0], aH[mi][1], aH[mi][2], aH[mi][3],
                       aBase + OFF_AH + (uint32_t)(mi * 16 * RSTR) + ko);
            #pragma unroll
            for (int p = 0; p < 2; p++)
                ldm_x4(bH[2*p][0], bH[2*p][1], bH[2*p+1][0], bH[2*p+1][1],
                       bBase + OFF_BH + (uint32_t)(p * 16 * RSTR) + ko);
            #pragma unroll
            for (int mi = 0; mi < 4; mi++)
                #pragma unroll
                for (int ni = 0; ni < 4; ni++)
                    mma16816(acc[mi][ni], aH[mi], bH[ni]);

            #pragma unroll
            for (int p = 0; p < 2; p++)
                ldm_x4(bL[2*p][0], bL[2*p][1], bL[2*p+1][0], bL[2*p+1][1],
                       bBase + OFF_BL + (uint32_t)(p * 16 * RSTR) + ko);
            #pragma unroll
            for (int mi = 0; mi < 4; mi++)
                #pragma unroll
                for (int ni = 0; ni < 4; ni++)
                    mma16816(acc[mi][ni], aH[mi], bL[ni]);

            #pragma unroll
            for (int mi = 0; mi < 4; mi++)
                ldm_x4(aL[mi][0], aL[mi][1], aL[mi][2], aL[mi][3],
                       aBase + OFF_AL + (uint32_t)(mi * 16 * RSTR) + ko);
            #pragma unroll
            for (int mi = 0; mi < 4; mi++)
                #pragma unroll
                for (int ni = 0; ni < 4; ni++)
                    mma16816(acc[mi][ni], aL[mi], bH[ni]);
        }
        __syncthreads();
    }

    // epilogue: bias (+sigmoid), direct stores (float2, 32B sectors)
    const int m_glob = bm * BM + wm0 + (lane >> 2);
    const int n_glob = bn * BN + wn0 + (lane & 3) * 2;

    float bv[4][2];
    #pragma unroll
    for (int ni = 0; ni < 4; ni++) {
        bv[ni][0] = __ldg(bias + n_glob + ni * 8);
        bv[ni][1] = __ldg(bias + n_glob + ni * 8 + 1);
    }

    #pragma unroll
    for (int mi = 0; mi < 4; mi++) {
        #pragma unroll
        for (int ni = 0; ni < 4; ni++) {
            float v0 = acc[mi][ni][0] + bv[ni][0];
            float v1 = acc[mi][ni][1] + bv[ni][1];
            float v2 = acc[mi][ni][2] + bv[ni][0];
            float v3 = acc[mi][ni][3] + bv[ni][1];
            if (z) { v0 = sigmoidf_(v0); v1 = sigmoidf_(v1);
                     v2 = sigmoidf_(v2); v3 = sigmoidf_(v3); }
            float2 lo_ = make_float2(v0, v1);
            float2 hi_ = make_float2(v2, v3);
            float* p0 = C + (size_t)(m_glob + mi * 16)     * DIM + n_glob + ni * 8;
            float* p1 = C + (size_t)(m_glob + mi * 16 + 8) * DIM + n_glob + ni * 8;
            *(float2*)p0 = lo_;
            *(float2*)p1 = hi_;
        }
    }
}

// ---------------- sequential scan (unchanged) ----------------
__global__ __launch_bounds__(256)
void scan_kernel(const float* __restrict__ h0,
                 const float* __restrict__ wx,
                 const float* __restrict__ gate,
                 float* __restrict__ out_o,
                 float* __restrict__ out_h)
{
    const int b    = blockIdx.x;
    const int tid  = threadIdx.x;
    const int lane = tid & 31;
    const int wid  = tid >> 5;
    const int d    = tid * 4;

    __shared__ float red[2][8];

    float4 h = *(const float4*)(h0 + b * DIM + d);
    *(float4*)(out_h + b * DIM + d) = h;

    const int base    = b * DIM + d;
    const int tstride = BATCH * DIM;

    float4 g = *(const float4*)(gate + base);
    float4 w = *(const float4*)(wx + base);

    for (int t = 0; t < T_STEPS; t++) {
        float4 gn, wn;
        if (t + 1 < T_STEPS) {
            const int nb = base + (t + 1) * tstride;
            gn = *(const float4*)(gate + nb);
            wn = *(const float4*)(wx + nb);
        }

        float4 hn;
        hn.x = fmaf(g.x, w.x, h.x);
        hn.y = fmaf(g.y, w.y, h.y);
        hn.z = fmaf(g.z, w.z, h.z);
        hn.w = fmaf(g.w, w.w, h.w);

        float s = hn.x * hn.x + hn.y * hn.y + hn.z * hn.z + hn.w * hn.w;
        #pragma unroll
        for (int o = 16; o > 0; o >>= 1)
            s += __shfl_xor_sync(0xffffffffu, s, o);
        if (lane == 0) red[t & 1][wid] = s;
        __syncthreads();
        float tot = 0.0f;
        #pragma unroll
        for (int i = 0; i < 8; i++) tot += red[t & 1][i];

        const float rstd = rsqrtf(tot * (1.0f / (float)DIM) + 1e-6f);
        h.x = hn.x * rstd; h.y = hn.y * rstd;
        h.z = hn.z * rstd; h.w = hn.w * rstd;

        float4 o4;
        o4.x = h.x * h.x * sigmoidf_(h.x);
        o4.y = h.y * h.y * sigmoidf_(h.y);
        o4.z = h.z * h.z * sigmoidf_(h.z);
        o4.w = h.w * h.w * sigmoidf_(h.w);

        const int ob = t * tstride + base;
        *(float4*)(out_o + ob) = o4;
        *(float4*)(out_h + ob + tstride) = h;

        g = gn; w = wn;
    }
}

// ---------------- launch ----------------
extern "C" void kernel_launch(void* const* d_in, const int* in_sizes, int n_in,
                              void* d_out, int out_size)
{
    const float* x  = (const float*)d_in[0];
    const float* h0 = (const float*)d_in[1];
    const float* W  = (const float*)d_in[2];
    const float* Wg = (const float*)d_in[3];
    const float* b  = (const float*)d_in[4];
    const float* bg = (const float*)d_in[5];

    float* out   = (float*)d_out;
    float* out_o = out;
    float* out_h = out + (size_t)T_STEPS * BATCH * DIM;

    __nv_bfloat16 *xhi, *xlo, *whi, *wlo, *vhi, *vlo;
    float *wxp, *gtp;
    cudaGetSymbolAddress((void**)&xhi, g_xhi);
    cudaGetSymbolAddress((void**)&xlo, g_xlo);
    cudaGetSymbolAddress((void**)&whi, g_whi);
    cudaGetSymbolAddress((void**)&wlo, g_wlo);
    cudaGetSymbolAddress((void**)&vhi, g_vhi);
    cudaGetSymbolAddress((void**)&vlo, g_vlo);
    cudaGetSymbolAddress((void**)&wxp, g_wx);
    cudaGetSymbolAddress((void**)&gtp, g_gate);

    {
        int n4 = M_TOT * DIM / 4;
        split_kernel<<<n4 / 256, 256>>>(x, xhi, xlo, n4);
        int w4 = DIM * DIM / 4;
        split_kernel<<<w4 / 256, 256>>>(W,  whi, wlo, w4);
        split_kernel<<<w4 / 256, 256>>>(Wg, vhi, vlo, w4);
    }

    cudaFuncSetAttribute(gemm_kernel, cudaFuncAttributeMaxDynamicSharedMemorySize, SMEM_TOTAL);
    dim3 grid(DIM / BN, M_TOT / BM, 2);   // (8, 256, 2) — bn fastest for A reuse
    gemm_kernel<<<grid, 256, SMEM_TOTAL>>>(xhi, xlo, whi, wlo, vhi, vlo, b, bg, wxp, gtp);

    scan_kernel<<<BATCH, 256>>>(h0, wxp, gtp, out_o, out_h);
}

// round 5
// speedup vs baseline: 1.7050x; 1.0102x over previous
#include <cuda_runtime.h>
#include <cuda_bf16.h>
#include <cstdint>

#define T_STEPS 2048
#define BATCH   16
#define DIM     1024
#define M_TOT   (T_STEPS * BATCH)   // 32768

// ---------------- GEMM tiling ----------------
#define BM 128
#define BN 128
#define BK 32
#define NCHUNK 96               // virtual K = 3072 (3 split phases x 32 chunks)
#define NSTAGES 4

#define RSTR 80                 // padded smem row stride in bytes (40 bf16)
#define MATB (128 * RSTR)       // 10240 bytes per 128x32 bf16 tile
#define OFF_A 0
#define OFF_B MATB
#define STG   (2 * MATB)        // 20480 per stage
#define SMEM_TOTAL (NSTAGES * STG)  // 81920 -> 2 CTAs/SM

// ---------------- scratch ----------------
__device__ __nv_bfloat16 g_xhi[(size_t)M_TOT * DIM];
__device__ __nv_bfloat16 g_xlo[(size_t)M_TOT * DIM];
__device__ __nv_bfloat16 g_whi[DIM * DIM], g_wlo[DIM * DIM];
__device__ __nv_bfloat16 g_vhi[DIM * DIM], g_vlo[DIM * DIM];
__device__ float g_wx[(size_t)M_TOT * DIM];
__device__ float g_gate[(size_t)M_TOT * DIM];

// ---------------- helpers ----------------
__device__ __forceinline__ uint32_t smem_u32(const void* p) {
    uint32_t a;
    asm("{ .reg .u64 t; cvta.to.shared.u64 t, %1; cvt.u32.u64 %0, t; }" : "=r"(a) : "l"(p));
    return a;
}
__device__ __forceinline__ void cpasync16(uint32_t dst, const void* src) {
    asm volatile("cp.async.cg.shared.global [%0], [%1], 16;" :: "r"(dst), "l"(src));
}
__device__ __forceinline__ void cp_commit() { asm volatile("cp.async.commit_group;"); }
__device__ __forceinline__ void cp_wait2()  { asm volatile("cp.async.wait_group 2;"); }

__device__ __forceinline__ void ldm_x4(uint32_t& r0, uint32_t& r1, uint32_t& r2, uint32_t& r3,
                                       uint32_t addr) {
    asm volatile("ldmatrix.sync.aligned.m8n8.x4.shared.b16 {%0,%1,%2,%3}, [%4];"
                 : "=r"(r0), "=r"(r1), "=r"(r2), "=r"(r3) : "r"(addr));
}
__device__ __forceinline__ void mma16816(float* c, const uint32_t* a, const uint32_t* b) {
    asm volatile(
        "mma.sync.aligned.m16n8k16.row.col.f32.bf16.bf16.f32 "
        "{%0,%1,%2,%3}, {%4,%5,%6,%7}, {%8,%9}, {%0,%1,%2,%3};"
        : "+f"(c[0]), "+f"(c[1]), "+f"(c[2]), "+f"(c[3])
        : "r"(a[0]), "r"(a[1]), "r"(a[2]), "r"(a[3]), "r"(b[0]), "r"(b[1]));
}
__device__ __forceinline__ float sigmoidf_(float v) {
    return 1.0f / (1.0f + __expf(-v));
}

// ---------------- fp32 -> bf16 hi/lo split ----------------
__global__ __launch_bounds__(256)
void split_kernel(const float* __restrict__ s,
                  __nv_bfloat16* __restrict__ hi,
                  __nv_bfloat16* __restrict__ lo, int n4)
{
    int i = blockIdx.x * blockDim.x + threadIdx.x;
    if (i >= n4) return;
    float4 v = ((const float4*)s)[i];
    float a[4] = {v.x, v.y, v.z, v.w};
    __nv_bfloat16 h[4], l[4];
    #pragma unroll
    for (int j = 0; j < 4; j++) {
        h[j] = __float2bfloat16(a[j]);
        l[j] = __float2bfloat16(a[j] - __bfloat162float(h[j]));
    }
    ((__nv_bfloat162*)hi)[i * 2 + 0] = __nv_bfloat162(h[0], h[1]);
    ((__nv_bfloat162*)hi)[i * 2 + 1] = __nv_bfloat162(h[2], h[3]);
    ((__nv_bfloat162*)lo)[i * 2 + 0] = __nv_bfloat162(l[0], l[1]);
    ((__nv_bfloat162*)lo)[i * 2 + 1] = __nv_bfloat162(l[2], l[3]);
}

// ---------------- single-pass split-K GEMM (virtual K = 3072) ----------------
// chunk i: phase p = i/32 selects (Ah,Bh) / (Ah,Bl) / (Al,Bh); kk = (i%32)*32
__device__ __forceinline__ void load_chunk(uint32_t sbase,
                                           const __nv_bfloat16* __restrict__ Ap,
                                           const __nv_bfloat16* __restrict__ Bp,
                                           int kk)
{
    const int tid = threadIdx.x;
    #pragma unroll
    for (int j = 0; j < 2; j++) {
        int c   = tid + j * 256;       // 0..511
        int row = c >> 2;              // 0..127
        int cc  = c & 3;               // 16B chunk within 64B row
        uint32_t so = (uint32_t)(row * RSTR + cc * 16);
        size_t   go = (size_t)row * DIM + kk + cc * 8;
        cpasync16(sbase + OFF_A + so, Ap + go);
        cpasync16(sbase + OFF_B + so, Bp + go);
    }
}

__global__ __launch_bounds__(256, 2)
void gemm_kernel(const __nv_bfloat16* __restrict__ xhi, const __nv_bfloat16* __restrict__ xlo,
                 const __nv_bfloat16* __restrict__ whi, const __nv_bfloat16* __restrict__ wlo,
                 const __nv_bfloat16* __restrict__ vhi, const __nv_bfloat16* __restrict__ vlo,
                 const float* __restrict__ bias0, const float* __restrict__ bias1,
                 float* __restrict__ wx, float* __restrict__ gate)
{
    extern __shared__ char smem[];
    const uint32_t sb = smem_u32(smem);
    const int tid  = threadIdx.x;
    const int wid  = tid >> 5;
    const int lane = tid & 31;
    const int bn = blockIdx.x, bm = blockIdx.y, z = blockIdx.z;

    const __nv_bfloat16* Ah = xhi + (size_t)bm * BM * DIM;
    const __nv_bfloat16* Al = xlo + (size_t)bm * BM * DIM;
    const __nv_bfloat16* Bh = (z ? vhi : whi) + (size_t)bn * BN * DIM;
    const __nv_bfloat16* Bl = (z ? vlo : wlo) + (size_t)bn * BN * DIM;
    const float* bias = z ? bias1 : bias0;
    float* C = z ? gate : wx;

    // per-chunk operand pointers (virtual K)
    const __nv_bfloat16* pa[3] = {Ah, Ah, Al};
    const __nv_bfloat16* pb[3] = {Bh, Bl, Bh};

    // warp tile: 2 x 4 warps, 64 x 32 each
    const int wm0 = (wid & 1) * 64;
    const int wn0 = (wid >> 1) * 32;

    const uint32_t a_lane = (uint32_t)((lane & 15) * RSTR + (lane >> 4) * 16);
    const int g = lane >> 3;
    const uint32_t b_lane = (uint32_t)(((g >> 1) * 8 + (lane & 7)) * RSTR + (g & 1) * 16);

    float acc[4][4][4];
    #pragma unroll
    for (int mi = 0; mi < 4; mi++)
        #pragma unroll
        for (int ni = 0; ni < 4; ni++)
            #pragma unroll
            for (int r = 0; r < 4; r++) acc[mi][ni][r] = 0.0f;

    // prologue: 3 chunks in flight
    #pragma unroll
    for (int p = 0; p < 3; p++) {
        load_chunk(sb + p * STG, pa[0], pb[0], p * BK);
        cp_commit();
    }

    for (int i = 0; i < NCHUNK; i++) {
        cp_wait2();
        __syncthreads();

        if (i + 3 < NCHUNK) {
            const int ni_ = i + 3;
            const int ph = ni_ >> 5;
            load_chunk(sb + (uint32_t)(ni_ & 3) * STG, pa[ph], pb[ph], (ni_ & 31) * BK);
        }
        cp_commit();

        const uint32_t stg = sb + (uint32_t)(i & 3) * STG;
        const uint32_t aBase = stg + OFF_A + (uint32_t)(wm0 * RSTR) + a_lane;
        const uint32_t bBase = stg + OFF_B + (uint32_t)(wn0 * RSTR) + b_lane;

        #pragma unroll
        for (int ks = 0; ks < 2; ks++) {
            const uint32_t ko = (uint32_t)(ks * 32);
            uint32_t aF[4][4], bF[4][2];
            #pragma unroll
            for (int mi = 0; mi < 4; mi++)
                ldm_x4(aF[mi][0], aF[mi][1], aF[mi][2], aF[mi][3],
                       aBase + (uint32_t)(mi * 16 * RSTR) + ko);
            #pragma unroll
            for (int p = 0; p < 2; p++)
                ldm_x4(bF[2*p][0], bF[2*p][1], bF[2*p+1][0], bF[2*p+1][1],
                       bBase + (uint32_t)(p * 16 * RSTR) + ko);
            #pragma unroll
            for (int mi = 0; mi < 4; mi++)
                #pragma unroll
                for (int ni = 0; ni < 4; ni++)
                    mma16816(acc[mi][ni], aF[mi], bF[ni]);
        }
        __syncthreads();
    }

    // epilogue: bias (+sigmoid), direct float2 stores
    const int m_glob = bm * BM + wm0 + (lane >> 2);
    const int n_glob = bn * BN + wn0 + (lane & 3) * 2;

    float bv[4][2];
    #pragma unroll
    for (int ni = 0; ni < 4; ni++) {
        bv[ni][0] = __ldg(bias + n_glob + ni * 8);
        bv[ni][1] = __ldg(bias + n_glob + ni * 8 + 1);
    }

    #pragma unroll
    for (int mi = 0; mi < 4; mi++) {
        #pragma unroll
        for (int ni = 0; ni < 4; ni++) {
            float v0 = acc[mi][ni][0] + bv[ni][0];
            float v1 = acc[mi][ni][1] + bv[ni][1];
            float v2 = acc[mi][ni][2] + bv[ni][0];
            float v3 = acc[mi][ni][3] + bv[ni][1];
            if (z) { v0 = sigmoidf_(v0); v1 = sigmoidf_(v1);
                     v2 = sigmoidf_(v2); v3 = sigmoidf_(v3); }
            float* p0 = C + (size_t)(m_glob + mi * 16)     * DIM + n_glob + ni * 8;
            float* p1 = C + (size_t)(m_glob + mi * 16 + 8) * DIM + n_glob + ni * 8;
            *(float2*)p0 = make_float2(v0, v1);
            *(float2*)p1 = make_float2(v2, v3);
        }
    }
}

// ---------------- sequential scan (unchanged) ----------------
__global__ __launch_bounds__(256)
void scan_kernel(const float* __restrict__ h0,
                 const float* __restrict__ wx,
                 const float* __restrict__ gate,
                 float* __restrict__ out_o,
                 float* __restrict__ out_h)
{
    const int b    = blockIdx.x;
    const int tid  = threadIdx.x;
    const int lane = tid & 31;
    const int wid  = tid >> 5;
    const int d    = tid * 4;

    __shared__ float red[2][8];

    float4 h = *(const float4*)(h0 + b * DIM + d);
    *(float4*)(out_h + b * DIM + d) = h;

    const int base    = b * DIM + d;
    const int tstride = BATCH * DIM;

    float4 g = *(const float4*)(gate + base);
    float4 w = *(const float4*)(wx + base);

    for (int t = 0; t < T_STEPS; t++) {
        float4 gn, wn;
        if (t + 1 < T_STEPS) {
            const int nb = base + (t + 1) * tstride;
            gn = *(const float4*)(gate + nb);
            wn = *(const float4*)(wx + nb);
        }

        float4 hn;
        hn.x = fmaf(g.x, w.x, h.x);
        hn.y = fmaf(g.y, w.y, h.y);
        hn.z = fmaf(g.z, w.z, h.z);
        hn.w = fmaf(g.w, w.w, h.w);

        float s = hn.x * hn.x + hn.y * hn.y + hn.z * hn.z + hn.w * hn.w;
        #pragma unroll
        for (int o = 16; o > 0; o >>= 1)
            s += __shfl_xor_sync(0xffffffffu, s, o);
        if (lane == 0) red[t & 1][wid] = s;
        __syncthreads();
        float tot = 0.0f;
        #pragma unroll
        for (int i = 0; i < 8; i++) tot += red[t & 1][i];

        const float rstd = rsqrtf(tot * (1.0f / (float)DIM) + 1e-6f);
        h.x = hn.x * rstd; h.y = hn.y * rstd;
        h.z = hn.z * rstd; h.w = hn.w * rstd;

        float4 o4;
        o4.x = h.x * h.x * sigmoidf_(h.x);
        o4.y = h.y * h.y * sigmoidf_(h.y);
        o4.z = h.z * h.z * sigmoidf_(h.z);
        o4.w = h.w * h.w * sigmoidf_(h.w);

        const int ob = t * tstride + base;
        *(float4*)(out_o + ob) = o4;
        *(float4*)(out_h + ob + tstride) = h;

        g = gn; w = wn;
    }
}

// ---------------- launch ----------------
extern "C" void kernel_launch(void* const* d_in, const int* in_sizes, int n_in,
                              void* d_out, int out_size)
{
    const float* x  = (const float*)d_in[0];
    const float* h0 = (const float*)d_in[1];
    const float* W  = (const float*)d_in[2];
    const float* Wg = (const float*)d_in[3];
    const float* b  = (const float*)d_in[4];
    const float* bg = (const float*)d_in[5];

    float* out   = (float*)d_out;
    float* out_o = out;
    float* out_h = out + (size_t)T_STEPS * BATCH * DIM;

    __nv_bfloat16 *xhi, *xlo, *whi, *wlo, *vhi, *vlo;
    float *wxp, *gtp;
    cudaGetSymbolAddress((void**)&xhi, g_xhi);
    cudaGetSymbolAddress((void**)&xlo, g_xlo);
    cudaGetSymbolAddress((void**)&whi, g_whi);
    cudaGetSymbolAddress((void**)&wlo, g_wlo);
    cudaGetSymbolAddress((void**)&vhi, g_vhi);
    cudaGetSymbolAddress((void**)&vlo, g_vlo);
    cudaGetSymbolAddress((void**)&wxp, g_wx);
    cudaGetSymbolAddress((void**)&gtp, g_gate);

    {
        int n4 = M_TOT * DIM / 4;
        split_kernel<<<n4 / 256, 256>>>(x, xhi, xlo, n4);
        int w4 = DIM * DIM / 4;
        split_kernel<<<w4 / 256, 256>>>(W,  whi, wlo, w4);
        split_kernel<<<w4 / 256, 256>>>(Wg, vhi, vlo, w4);
    }

    cudaFuncSetAttribute(gemm_kernel, cudaFuncAttributeMaxDynamicSharedMemorySize, SMEM_TOTAL);
    dim3 grid(DIM / BN, M_TOT / BM, 2);   // (8, 256, 2) — bn fastest for A reuse
    gemm_kernel<<<grid, 256, SMEM_TOTAL>>>(xhi, xlo, whi, wlo, vhi, vlo, b, bg, wxp, gtp);

    scan_kernel<<<BATCH, 256>>>(h0, wxp, gtp, out_o, out_h);
}